// round 1
// baseline (speedup 1.0000x reference)
#include <cuda_runtime.h>

#define BATCH 2
#define SEQ   2048
#define DMODEL 2048
#define NH    32
#define NG    8
#define DKH   64
#define GDK   (NG * DKH)   // 512
#define MROWS (BATCH * SEQ) // 4096

// ---------------- scratch (no cudaMalloc allowed) ----------------
__device__ float g_Q[MROWS * DMODEL];  // [B*S, H*dk]
__device__ float g_K[MROWS * GDK];     // [B*S, G*dk]
__device__ float g_V[MROWS * GDK];     // [B*S, G*dk]
__device__ float g_C[MROWS * DMODEL];  // attention context

// ---------------- SGEMM: C = A[MxK] * B[KxN] + bias[N] ----------------
// 128x128 tile, BK=16, 256 threads, 8x8 micro-tile per thread.
// Requires M%128==0, N%128==0, K%16==0 (true for all calls here).
__global__ __launch_bounds__(256) void sgemm_bias_kernel(
    const float* __restrict__ A, const float* __restrict__ B,
    const float* __restrict__ bias, float* __restrict__ C,
    int M, int N, int K)
{
    __shared__ float As[16][128];   // transposed A tile: As[k][m]
    __shared__ float Bs[16][128];   // natural B tile:    Bs[k][n]

    const int bn = blockIdx.x * 128;
    const int bm = blockIdx.y * 128;
    const int tid = threadIdx.x;
    const int tx = tid & 15;
    const int ty = tid >> 4;

    float acc[8][8];
#pragma unroll
    for (int i = 0; i < 8; i++)
#pragma unroll
        for (int j = 0; j < 8; j++) acc[i][j] = 0.0f;

    for (int kt = 0; kt < K; kt += 16) {
        // --- load A tile (128 rows x 16 cols) transposed, 2 float4 per thread
#pragma unroll
        for (int i = 0; i < 2; i++) {
            int idx = tid * 2 + i;            // 0..511
            int ar  = idx >> 2;               // 0..127
            int ac4 = idx & 3;                // 0..3
            float4 av = *(const float4*)(A + (size_t)(bm + ar) * K + kt + ac4 * 4);
            As[ac4 * 4 + 0][ar] = av.x;
            As[ac4 * 4 + 1][ar] = av.y;
            As[ac4 * 4 + 2][ar] = av.z;
            As[ac4 * 4 + 3][ar] = av.w;
            // --- load B tile (16 rows x 128 cols)
            int br  = idx >> 5;               // 0..15
            int bc4 = idx & 31;               // 0..31
            *(float4*)(&Bs[br][bc4 * 4]) =
                *(const float4*)(B + (size_t)(kt + br) * N + bn + bc4 * 4);
        }
        __syncthreads();

#pragma unroll
        for (int kk = 0; kk < 16; kk++) {
            float a[8], b[8];
            float4 a0 = *(float4*)(&As[kk][ty * 4]);
            float4 a1 = *(float4*)(&As[kk][ty * 4 + 64]);
            float4 b0 = *(float4*)(&Bs[kk][tx * 4]);
            float4 b1 = *(float4*)(&Bs[kk][tx * 4 + 64]);
            a[0]=a0.x; a[1]=a0.y; a[2]=a0.z; a[3]=a0.w;
            a[4]=a1.x; a[5]=a1.y; a[6]=a1.z; a[7]=a1.w;
            b[0]=b0.x; b[1]=b0.y; b[2]=b0.z; b[3]=b0.w;
            b[4]=b1.x; b[5]=b1.y; b[6]=b1.z; b[7]=b1.w;
#pragma unroll
            for (int i = 0; i < 8; i++)
#pragma unroll
                for (int j = 0; j < 8; j++) acc[i][j] += a[i] * b[j];
        }
        __syncthreads();
    }

#pragma unroll
    for (int i = 0; i < 8; i++) {
        int r = bm + ty * 4 + ((i < 4) ? i : (64 + i - 4));
#pragma unroll
        for (int j = 0; j < 8; j++) {
            int c = bn + tx * 4 + ((j < 4) ? j : (64 + j - 4));
            C[(size_t)r * N + c] = acc[i][j] + bias[c];
        }
    }
}

// ---------------- Flash attention (fp32, online softmax) ----------------
// grid: (S/64, H, B); 256 threads (16x16); each thread owns 4x4 tiles.
// Dynamic smem layout (floats):
//   Qs  [64][64]  natural (i, d)                    : 4096
//   KPs [64][65]  Ks transposed (d, j) -> later Ps natural (i, j) : 4160
//   Vs  [64][64]  natural (j, d)                    : 4096
#define SM_Q  0
#define SM_KP 4096
#define SM_V  8256
#define ATTN_SMEM_FLOATS 12352

__global__ __launch_bounds__(256) void gqa_attn_kernel(
    const float* __restrict__ Q, const float* __restrict__ Kb,
    const float* __restrict__ Vb, float* __restrict__ O)
{
    extern __shared__ float sm[];
    float* Qs  = sm + SM_Q;
    float* KPs = sm + SM_KP;
    float* Vs  = sm + SM_V;

    const int h  = blockIdx.y;
    const int b  = blockIdx.z;
    const int g  = h >> 2;                 // h / GROUP_SIZE
    const int q0 = blockIdx.x * 64;
    const int tid = threadIdx.x;
    const int tx = tid & 15;
    const int ty = tid >> 4;

    // load Q tile: rows q0..q0+63 of head h
    for (int e = tid; e < 4096; e += 256) {
        int i = e >> 6, d = e & 63;
        Qs[i * 64 + d] = Q[(size_t)(b * SEQ + q0 + i) * DMODEL + h * DKH + d];
    }

    float m_run[4], l_run[4], oacc[4][4];
#pragma unroll
    for (int i = 0; i < 4; i++) {
        m_run[i] = -1e30f; l_run[i] = 0.0f;
#pragma unroll
        for (int j = 0; j < 4; j++) oacc[i][j] = 0.0f;
    }

    const float scale = 0.125f;  // 1/sqrt(64)

    for (int kt = 0; kt < SEQ; kt += 64) {
        // load K (transposed, padded 65) and V (natural)
        for (int e = tid; e < 4096; e += 256) {
            int j = e >> 6, d = e & 63;
            size_t gidx = (size_t)(b * SEQ + kt + j) * GDK + g * DKH + d;
            KPs[d * 65 + j] = Kb[gidx];
            Vs[j * 64 + d]  = Vb[gidx];
        }
        __syncthreads();

        // scores: s[i][j] = sum_d Q[4ty+i][d] * K[4tx+j][d]
        float s[4][4];
#pragma unroll
        for (int i = 0; i < 4; i++)
#pragma unroll
            for (int j = 0; j < 4; j++) s[i][j] = 0.0f;

#pragma unroll 4
        for (int d = 0; d < 64; d++) {
            float qv[4], kv[4];
#pragma unroll
            for (int i = 0; i < 4; i++) qv[i] = Qs[(4 * ty + i) * 64 + d];
#pragma unroll
            for (int j = 0; j < 4; j++) kv[j] = KPs[d * 65 + 4 * tx + j];
#pragma unroll
            for (int i = 0; i < 4; i++)
#pragma unroll
                for (int j = 0; j < 4; j++) s[i][j] += qv[i] * kv[j];
        }
        __syncthreads();   // done reading Ks; buffer will be reused for P

        // online softmax: row max across the 16 tx lanes (width-16 shfl)
        float mnew[4], ls[4];
#pragma unroll
        for (int i = 0; i < 4; i++) {
#pragma unroll
            for (int j = 0; j < 4; j++) s[i][j] *= scale;
            float rm = fmaxf(fmaxf(s[i][0], s[i][1]), fmaxf(s[i][2], s[i][3]));
#pragma unroll
            for (int o = 8; o > 0; o >>= 1)
                rm = fmaxf(rm, __shfl_xor_sync(0xffffffffu, rm, o, 16));
            mnew[i] = fmaxf(m_run[i], rm);
        }

        // exp, write P (natural [i][j], stride 65), partial row sums
#pragma unroll
        for (int i = 0; i < 4; i++) {
            float acc = 0.0f;
#pragma unroll
            for (int j = 0; j < 4; j++) {
                float p = __expf(s[i][j] - mnew[i]);
                KPs[(4 * ty + i) * 65 + 4 * tx + j] = p;
                acc += p;
            }
            ls[i] = acc;
        }
#pragma unroll
        for (int i = 0; i < 4; i++) {
#pragma unroll
            for (int o = 8; o > 0; o >>= 1)
                ls[i] += __shfl_xor_sync(0xffffffffu, ls[i], o, 16);
            float alpha = __expf(m_run[i] - mnew[i]);
            l_run[i] = l_run[i] * alpha + ls[i];
            m_run[i] = mnew[i];
#pragma unroll
            for (int j = 0; j < 4; j++) oacc[i][j] *= alpha;
        }
        __syncthreads();   // P visible to all

        // O[i][dv] += sum_j P[4ty+i][j] * V[j][4tx+dv]
#pragma unroll 4
        for (int j = 0; j < 64; j++) {
            float pv[4];
#pragma unroll
            for (int i = 0; i < 4; i++) pv[i] = KPs[(4 * ty + i) * 65 + j];
            float4 vv = *(float4*)(&Vs[j * 64 + 4 * tx]);
            float vr[4] = {vv.x, vv.y, vv.z, vv.w};
#pragma unroll
            for (int i = 0; i < 4; i++)
#pragma unroll
                for (int jj = 0; jj < 4; jj++) oacc[i][jj] += pv[i] * vr[jj];
        }
        __syncthreads();   // safe to reload K/V next tile
    }

    // epilogue: ctx[b, q, h*64 + dv] = O / l
#pragma unroll
    for (int i = 0; i < 4; i++) {
        float inv_l = 1.0f / l_run[i];
#pragma unroll
        for (int j = 0; j < 4; j++) {
            O[(size_t)(b * SEQ + q0 + 4 * ty + i) * DMODEL + h * DKH + 4 * tx + j] =
                oacc[i][j] * inv_l;
        }
    }
}

// ---------------- host ----------------
extern "C" void kernel_launch(void* const* d_in, const int* in_sizes, int n_in,
                              void* d_out, int out_size)
{
    const float* x  = (const float*)d_in[0];
    const float* Wq = (const float*)d_in[1];
    const float* bq = (const float*)d_in[2];
    const float* Wk = (const float*)d_in[3];
    const float* bk = (const float*)d_in[4];
    const float* Wv = (const float*)d_in[5];
    const float* bv = (const float*)d_in[6];
    const float* Wo = (const float*)d_in[7];
    const float* bo = (const float*)d_in[8];
    float* out = (float*)d_out;

    float *Q, *K, *V, *C;
    cudaGetSymbolAddress((void**)&Q, g_Q);
    cudaGetSymbolAddress((void**)&K, g_K);
    cudaGetSymbolAddress((void**)&V, g_V);
    cudaGetSymbolAddress((void**)&C, g_C);

    const int attn_smem = ATTN_SMEM_FLOATS * (int)sizeof(float); // 49408 B
    cudaFuncSetAttribute(gqa_attn_kernel,
                         cudaFuncAttributeMaxDynamicSharedMemorySize, attn_smem);

    // projections
    sgemm_bias_kernel<<<dim3(DMODEL / 128, MROWS / 128), 256>>>(
        x, Wq, bq, Q, MROWS, DMODEL, DMODEL);
    sgemm_bias_kernel<<<dim3(GDK / 128, MROWS / 128), 256>>>(
        x, Wk, bk, K, MROWS, GDK, DMODEL);
    sgemm_bias_kernel<<<dim3(GDK / 128, MROWS / 128), 256>>>(
        x, Wv, bv, V, MROWS, GDK, DMODEL);

    // attention
    gqa_attn_kernel<<<dim3(SEQ / 64, NH, BATCH), 256, attn_smem>>>(Q, K, V, C);

    // output projection
    sgemm_bias_kernel<<<dim3(DMODEL / 128, MROWS / 128), 256>>>(
        C, Wo, bo, out, MROWS, DMODEL, DMODEL);
}

// round 2
// speedup vs baseline: 2.5956x; 2.5956x over previous
#include <cuda_runtime.h>

#define BATCH 2
#define SEQ   2048
#define DMODEL 2048
#define NH    32
#define NG    8
#define DKH   64
#define GDK   (NG * DKH)    // 512
#define MROWS (BATCH * SEQ) // 4096

// ---------------- scratch (no cudaMalloc allowed) ----------------
__device__ float g_Q[MROWS * DMODEL];
__device__ float g_K[MROWS * GDK];
__device__ float g_V[MROWS * GDK];
__device__ float g_C[MROWS * DMODEL];

// ---------------- tf32 helpers ----------------
__device__ __forceinline__ unsigned f2tf32(float x) {
    unsigned r; asm("cvt.rna.tf32.f32 %0, %1;" : "=r"(r) : "f"(x)); return r;
}
__device__ __forceinline__ void mma_tf32(float* d, const unsigned* a, const unsigned* b) {
    asm volatile(
        "mma.sync.aligned.m16n8k8.row.col.f32.tf32.tf32.f32 "
        "{%0,%1,%2,%3}, {%4,%5,%6,%7}, {%8,%9}, {%0,%1,%2,%3};"
        : "+f"(d[0]), "+f"(d[1]), "+f"(d[2]), "+f"(d[3])
        : "r"(a[0]), "r"(a[1]), "r"(a[2]), "r"(a[3]), "r"(b[0]), "r"(b[1]));
}

// ---------------- tf32 GEMM: C = A[MxK]*B[KxN] + bias ----------------
// block 128x128, BK=16, 256 threads = 8 warps (2x4), warp tile 64x32.
#define AS_STRIDE 20   // [m][k] pad: banks conflict-free for frag loads
#define BS_STRIDE 136  // [k][n] pad: 136 % 32 == 8 -> conflict-free B frags

__global__ __launch_bounds__(256) void gemm_tf32_kernel(
    const float* __restrict__ A, const float* __restrict__ B,
    const float* __restrict__ bias, float* __restrict__ C,
    int M, int N, int K)
{
    __shared__ unsigned As[128 * AS_STRIDE];
    __shared__ unsigned Bs[16 * BS_STRIDE];

    const int tid  = threadIdx.x;
    const int warp = tid >> 5;
    const int lane = tid & 31;
    const int grp  = lane >> 2;   // 0..7
    const int tig  = lane & 3;    // 0..3
    const int bm = blockIdx.y * 128;
    const int bn = blockIdx.x * 128;
    const int wm = (warp >> 2) * 64;   // 0 / 64
    const int wn = (warp & 3) * 32;    // 0/32/64/96

    float acc[4][4][4];
#pragma unroll
    for (int mt = 0; mt < 4; mt++)
#pragma unroll
        for (int nt = 0; nt < 4; nt++)
#pragma unroll
            for (int f = 0; f < 4; f++) acc[mt][nt][f] = 0.0f;

    for (int kt = 0; kt < K; kt += 16) {
#pragma unroll
        for (int i = 0; i < 2; i++) {
            int idx = tid * 2 + i;          // 0..511
            // A tile: 128 rows x 16 k, as [m][k]
            int ar  = idx >> 2;
            int ac4 = idx & 3;
            float4 av = *(const float4*)(A + (size_t)(bm + ar) * K + kt + ac4 * 4);
            uint4 ap = make_uint4(f2tf32(av.x), f2tf32(av.y), f2tf32(av.z), f2tf32(av.w));
            *(uint4*)&As[ar * AS_STRIDE + ac4 * 4] = ap;
            // B tile: 16 rows x 128 n, as [k][n]
            int br  = idx >> 5;
            int bc4 = idx & 31;
            float4 bv = *(const float4*)(B + (size_t)(kt + br) * N + bn + bc4 * 4);
            uint4 bp = make_uint4(f2tf32(bv.x), f2tf32(bv.y), f2tf32(bv.z), f2tf32(bv.w));
            *(uint4*)&Bs[br * BS_STRIDE + bc4 * 4] = bp;
        }
        __syncthreads();

#pragma unroll
        for (int ks = 0; ks < 16; ks += 8) {
            unsigned af[4][4], bf[4][2];
#pragma unroll
            for (int mt = 0; mt < 4; mt++) {
                int r0 = wm + mt * 16 + grp;
                af[mt][0] = As[r0 * AS_STRIDE + ks + tig];
                af[mt][1] = As[(r0 + 8) * AS_STRIDE + ks + tig];
                af[mt][2] = As[r0 * AS_STRIDE + ks + tig + 4];
                af[mt][3] = As[(r0 + 8) * AS_STRIDE + ks + tig + 4];
            }
#pragma unroll
            for (int nt = 0; nt < 4; nt++) {
                int c0 = wn + nt * 8 + grp;
                bf[nt][0] = Bs[(ks + tig) * BS_STRIDE + c0];
                bf[nt][1] = Bs[(ks + tig + 4) * BS_STRIDE + c0];
            }
#pragma unroll
            for (int mt = 0; mt < 4; mt++)
#pragma unroll
                for (int nt = 0; nt < 4; nt++)
                    mma_tf32(acc[mt][nt], af[mt], bf[nt]);
        }
        __syncthreads();
    }

    // epilogue with bias
#pragma unroll
    for (int mt = 0; mt < 4; mt++) {
        int r0 = bm + wm + mt * 16 + grp;
#pragma unroll
        for (int nt = 0; nt < 4; nt++) {
            int c0 = bn + wn + nt * 8 + 2 * tig;
            float b0 = bias[c0], b1 = bias[c0 + 1];
            float2 v0 = make_float2(acc[mt][nt][0] + b0, acc[mt][nt][1] + b1);
            float2 v1 = make_float2(acc[mt][nt][2] + b0, acc[mt][nt][3] + b1);
            *(float2*)(C + (size_t)r0 * N + c0) = v0;
            *(float2*)(C + (size_t)(r0 + 8) * N + c0) = v1;
        }
    }
}

// ---------------- flash attention, tf32 mma ----------------
// block: 128 threads = 4 warps; 64 queries per block; key tiles of 64.
// warp w owns query rows [w*16, w*16+16).
// smem (dynamic): Qs[64*68] tf32, KPs[64*68] (K then P) tf32, Vs[64*72] tf32
#define QS_STRIDE 68
#define VS_STRIDE 72
#define SM_QOFF 0
#define SM_KOFF (64 * QS_STRIDE)
#define SM_VOFF (SM_KOFF + 64 * QS_STRIDE)
#define ATTN_SMEM_WORDS (SM_VOFF + 64 * VS_STRIDE)   // 13312 words = 53248 B

__global__ __launch_bounds__(128) void gqa_attn_tf32_kernel(
    const float* __restrict__ Q, const float* __restrict__ Kb,
    const float* __restrict__ Vb, float* __restrict__ O)
{
    extern __shared__ unsigned sm[];
    unsigned* Qs  = sm + SM_QOFF;
    unsigned* KPs = sm + SM_KOFF;
    unsigned* Vs  = sm + SM_VOFF;

    const int h  = blockIdx.y;
    const int b  = blockIdx.z;
    const int g  = h >> 2;
    const int q0 = blockIdx.x * 64;
    const int tid  = threadIdx.x;
    const int warp = tid >> 5;
    const int lane = tid & 31;
    const int grp  = lane >> 2;
    const int tig  = lane & 3;
    const int rA = warp * 16 + grp;       // fragment row A (within 64)
    // rB = rA + 8

    // load Q tile (tf32): 64 rows x 64 cols
    for (int e = tid; e < 1024; e += 128) {
        int q = e >> 4, d4 = e & 15;
        float4 v = *(const float4*)(Q + (size_t)(b * SEQ + q0 + q) * DMODEL + h * DKH + d4 * 4);
        *(uint4*)&Qs[q * QS_STRIDE + d4 * 4] =
            make_uint4(f2tf32(v.x), f2tf32(v.y), f2tf32(v.z), f2tf32(v.w));
    }

    float oacc[8][4];
#pragma unroll
    for (int nt = 0; nt < 8; nt++)
#pragma unroll
        for (int f = 0; f < 4; f++) oacc[nt][f] = 0.0f;
    float mA = -1e30f, mB = -1e30f, lA = 0.0f, lB = 0.0f;
    const float scale = 0.125f;

    for (int kt = 0; kt < SEQ; kt += 64) {
        // load K, V tiles (tf32)
        for (int e = tid; e < 1024; e += 128) {
            int j = e >> 4, d4 = e & 15;
            size_t gidx = (size_t)(b * SEQ + kt + j) * GDK + g * DKH + d4 * 4;
            float4 kv = *(const float4*)(Kb + gidx);
            float4 vv = *(const float4*)(Vb + gidx);
            *(uint4*)&KPs[j * QS_STRIDE + d4 * 4] =
                make_uint4(f2tf32(kv.x), f2tf32(kv.y), f2tf32(kv.z), f2tf32(kv.w));
            *(uint4*)&Vs[j * VS_STRIDE + d4 * 4] =
                make_uint4(f2tf32(vv.x), f2tf32(vv.y), f2tf32(vv.z), f2tf32(vv.w));
        }
        __syncthreads();

        // S = Q * K^T  (warp's 16 rows x 64 key cols)
        float sacc[8][4];
#pragma unroll
        for (int nt = 0; nt < 8; nt++)
#pragma unroll
            for (int f = 0; f < 4; f++) sacc[nt][f] = 0.0f;

#pragma unroll
        for (int ks = 0; ks < 8; ks++) {
            int d = ks * 8;
            unsigned af[4];
            af[0] = Qs[rA * QS_STRIDE + d + tig];
            af[1] = Qs[(rA + 8) * QS_STRIDE + d + tig];
            af[2] = Qs[rA * QS_STRIDE + d + tig + 4];
            af[3] = Qs[(rA + 8) * QS_STRIDE + d + tig + 4];
#pragma unroll
            for (int nt = 0; nt < 8; nt++) {
                unsigned bf[2];
                bf[0] = KPs[(nt * 8 + grp) * QS_STRIDE + d + tig];
                bf[1] = KPs[(nt * 8 + grp) * QS_STRIDE + d + tig + 4];
                mma_tf32(sacc[nt], af, bf);
            }
        }
        __syncthreads();   // K buffer free; will hold P

        // online softmax on fragment rows
        float rmaxA = -1e30f, rmaxB = -1e30f;
#pragma unroll
        for (int nt = 0; nt < 8; nt++) {
#pragma unroll
            for (int f = 0; f < 4; f++) sacc[nt][f] *= scale;
            rmaxA = fmaxf(rmaxA, fmaxf(sacc[nt][0], sacc[nt][1]));
            rmaxB = fmaxf(rmaxB, fmaxf(sacc[nt][2], sacc[nt][3]));
        }
#pragma unroll
        for (int o = 1; o <= 2; o <<= 1) {
            rmaxA = fmaxf(rmaxA, __shfl_xor_sync(0xffffffffu, rmaxA, o));
            rmaxB = fmaxf(rmaxB, __shfl_xor_sync(0xffffffffu, rmaxB, o));
        }
        float mnA = fmaxf(mA, rmaxA), mnB = fmaxf(mB, rmaxB);

        float lsA = 0.0f, lsB = 0.0f;
#pragma unroll
        for (int nt = 0; nt < 8; nt++) {
            float p0 = __expf(sacc[nt][0] - mnA);
            float p1 = __expf(sacc[nt][1] - mnA);
            float p2 = __expf(sacc[nt][2] - mnB);
            float p3 = __expf(sacc[nt][3] - mnB);
            lsA += p0 + p1;  lsB += p2 + p3;
            int c = nt * 8 + 2 * tig;
            KPs[rA * QS_STRIDE + c]       = f2tf32(p0);
            KPs[rA * QS_STRIDE + c + 1]   = f2tf32(p1);
            KPs[(rA + 8) * QS_STRIDE + c]     = f2tf32(p2);
            KPs[(rA + 8) * QS_STRIDE + c + 1] = f2tf32(p3);
        }
#pragma unroll
        for (int o = 1; o <= 2; o <<= 1) {
            lsA += __shfl_xor_sync(0xffffffffu, lsA, o);
            lsB += __shfl_xor_sync(0xffffffffu, lsB, o);
        }
        float alA = __expf(mA - mnA), alB = __expf(mB - mnB);
        lA = lA * alA + lsA;  lB = lB * alB + lsB;
        mA = mnA;             mB = mnB;
#pragma unroll
        for (int nt = 0; nt < 8; nt++) {
            oacc[nt][0] *= alA; oacc[nt][1] *= alA;
            oacc[nt][2] *= alB; oacc[nt][3] *= alB;
        }
        __syncwarp();   // P rows visible within warp

        // O += P * V   (warp's 16 rows x 64 dv cols)
#pragma unroll
        for (int ks = 0; ks < 8; ks++) {
            int j = ks * 8;
            unsigned af[4];
            af[0] = KPs[rA * QS_STRIDE + j + tig];
            af[1] = KPs[(rA + 8) * QS_STRIDE + j + tig];
            af[2] = KPs[rA * QS_STRIDE + j + tig + 4];
            af[3] = KPs[(rA + 8) * QS_STRIDE + j + tig + 4];
#pragma unroll
            for (int nt = 0; nt < 8; nt++) {
                unsigned bf[2];
                bf[0] = Vs[(j + tig) * VS_STRIDE + nt * 8 + grp];
                bf[1] = Vs[(j + tig + 4) * VS_STRIDE + nt * 8 + grp];
                mma_tf32(oacc[nt], af, bf);
            }
        }
        __syncthreads();   // done with P and V; next tile may overwrite
    }

    // epilogue
    float invA = 1.0f / lA, invB = 1.0f / lB;
    size_t rowA = (size_t)(b * SEQ + q0 + rA) * DMODEL + h * DKH;
    size_t rowB = rowA + (size_t)8 * DMODEL;
#pragma unroll
    for (int nt = 0; nt < 8; nt++) {
        int c = nt * 8 + 2 * tig;
        *(float2*)(O + rowA + c) = make_float2(oacc[nt][0] * invA, oacc[nt][1] * invA);
        *(float2*)(O + rowB + c) = make_float2(oacc[nt][2] * invB, oacc[nt][3] * invB);
    }
}

// ---------------- host ----------------
extern "C" void kernel_launch(void* const* d_in, const int* in_sizes, int n_in,
                              void* d_out, int out_size)
{
    const float* x  = (const float*)d_in[0];
    const float* Wq = (const float*)d_in[1];
    const float* bq = (const float*)d_in[2];
    const float* Wk = (const float*)d_in[3];
    const float* bk = (const float*)d_in[4];
    const float* Wv = (const float*)d_in[5];
    const float* bv = (const float*)d_in[6];
    const float* Wo = (const float*)d_in[7];
    const float* bo = (const float*)d_in[8];
    float* out = (float*)d_out;

    float *Q, *K, *V, *C;
    cudaGetSymbolAddress((void**)&Q, g_Q);
    cudaGetSymbolAddress((void**)&K, g_K);
    cudaGetSymbolAddress((void**)&V, g_V);
    cudaGetSymbolAddress((void**)&C, g_C);

    const int attn_smem = ATTN_SMEM_WORDS * (int)sizeof(unsigned);  // 53248 B
    cudaFuncSetAttribute(gqa_attn_tf32_kernel,
                         cudaFuncAttributeMaxDynamicSharedMemorySize, attn_smem);

    gemm_tf32_kernel<<<dim3(DMODEL / 128, MROWS / 128), 256>>>(
        x, Wq, bq, Q, MROWS, DMODEL, DMODEL);
    gemm_tf32_kernel<<<dim3(GDK / 128, MROWS / 128), 256>>>(
        x, Wk, bk, K, MROWS, GDK, DMODEL);
    gemm_tf32_kernel<<<dim3(GDK / 128, MROWS / 128), 256>>>(
        x, Wv, bv, V, MROWS, GDK, DMODEL);

    gqa_attn_tf32_kernel<<<dim3(SEQ / 64, NH, BATCH), 128, attn_smem>>>(Q, K, V, C);

    gemm_tf32_kernel<<<dim3(DMODEL / 128, MROWS / 128), 256>>>(
        C, Wo, bo, out, MROWS, DMODEL, DMODEL);
}

// round 6
// speedup vs baseline: 3.3859x; 1.3045x over previous
#include <cuda_runtime.h>

#define BATCH 2
#define SEQ   2048
#define DMODEL 2048
#define NH    32
#define NG    8
#define DKH   64
#define GDK   (NG * DKH)    // 512
#define MROWS (BATCH * SEQ) // 4096

// ---------------- scratch (no cudaMalloc allowed) ----------------
// everything tf32-as-uint32
__device__ unsigned g_xt [MROWS * DMODEL];
__device__ unsigned g_Qt [MROWS * DMODEL];
__device__ unsigned g_Kt [MROWS * GDK];
__device__ unsigned g_Vt [MROWS * GDK];
__device__ unsigned g_Ct [MROWS * DMODEL];
__device__ unsigned g_Wqt[DMODEL * DMODEL];
__device__ unsigned g_Wkt[DMODEL * GDK];
__device__ unsigned g_Wvt[DMODEL * GDK];
__device__ unsigned g_Wot[DMODEL * DMODEL];

// ---------------- helpers ----------------
__device__ __forceinline__ unsigned f2tf32(float x) {
    unsigned r; asm("cvt.rna.tf32.f32 %0, %1;" : "=r"(r) : "f"(x)); return r;
}
__device__ __forceinline__ void mma_tf32(float* d, const unsigned* a, const unsigned* b) {
    asm volatile(
        "mma.sync.aligned.m16n8k8.row.col.f32.tf32.tf32.f32 "
        "{%0,%1,%2,%3}, {%4,%5,%6,%7}, {%8,%9}, {%0,%1,%2,%3};"
        : "+f"(d[0]), "+f"(d[1]), "+f"(d[2]), "+f"(d[3])
        : "r"(a[0]), "r"(a[1]), "r"(a[2]), "r"(a[3]), "r"(b[0]), "r"(b[1]));
}
__device__ __forceinline__ unsigned smem_u32(const void* p) {
    unsigned a;
    asm("{ .reg .u64 t; cvta.to.shared.u64 t, %1; cvt.u32.u64 %0, t; }" : "=r"(a) : "l"(p));
    return a;
}
__device__ __forceinline__ void cp16(unsigned saddr, const void* g) {
    asm volatile("cp.async.cg.shared.global [%0], [%1], 16;" :: "r"(saddr), "l"(g));
}
#define CP_COMMIT() asm volatile("cp.async.commit_group;" ::: "memory")
#define CP_WAIT(n)  asm volatile("cp.async.wait_group %0;" :: "n"(n) : "memory")

// ---------------- fp32 -> tf32-word conversion ----------------
__global__ __launch_bounds__(256) void cvt_tf32_kernel(
    const float* __restrict__ in, unsigned* __restrict__ out, int n4)
{
    int i = blockIdx.x * blockDim.x + threadIdx.x;
    if (i >= n4) return;
    float4 v = ((const float4*)in)[i];
    ((uint4*)out)[i] = make_uint4(f2tf32(v.x), f2tf32(v.y), f2tf32(v.z), f2tf32(v.w));
}

// ---------------- tf32 GEMM with cp.async double buffer ----------------
// C[M,N] = A[M,K] * B[K,N] + bias.  A,B are tf32 words. BK=32.
// 256 threads = 8 warps (2x4), warp tile 64x32, 16 m16n8k8 mmas per k-step.
#define AST 36                      // A smem stride (words)
#define BST 136                     // B smem stride (words)
#define A_WORDS (128 * AST)         // 4608
#define B_WORDS (32 * BST)          // 4352
#define STG_WORDS (A_WORDS + B_WORDS)
#define GEMM_SMEM (2 * STG_WORDS * 4)   // 71680 B

template <bool OUT_TF32>
__global__ __launch_bounds__(256) void gemm_tf32_cp_kernel(
    const unsigned* __restrict__ A, const unsigned* __restrict__ B,
    const float* __restrict__ bias, void* __restrict__ Cout, int N, int K)
{
    extern __shared__ unsigned sm[];
    const unsigned sbase = smem_u32(sm);
    const int tid  = threadIdx.x;
    const int warp = tid >> 5;
    const int lane = tid & 31;
    const int grp  = lane >> 2;
    const int tig  = lane & 3;
    const int bm = blockIdx.y * 128;
    const int bn = blockIdx.x * 128;
    const int wm = (warp >> 2) * 64;
    const int wn = (warp & 3) * 32;

    float acc[4][4][4];
#pragma unroll
    for (int mt = 0; mt < 4; mt++)
#pragma unroll
        for (int nt = 0; nt < 4; nt++)
#pragma unroll
            for (int f = 0; f < 4; f++) acc[mt][nt][f] = 0.0f;

    const int NC = K >> 5;   // chunks of 32

    auto load_chunk = [&](int kc, int st) {
        unsigned abase = sbase + (st * STG_WORDS) * 4;
        unsigned bbase = abase + A_WORDS * 4;
        const unsigned* gA = A + (size_t)bm * K + kc * 32;
        const unsigned* gB = B + (size_t)(kc * 32) * N + bn;
#pragma unroll
        for (int it = 0; it < 4; it++) {
            int i = tid + it * 256;          // 0..1023
            int m  = i >> 3, k4 = i & 7;     // A: 128 rows x 8 chunks
            cp16(abase + (m * AST + k4 * 4) * 4, gA + (size_t)m * K + k4 * 4);
            int k  = i >> 5, n4 = i & 31;    // B: 32 rows x 32 chunks
            cp16(bbase + (k * BST + n4 * 4) * 4, gB + (size_t)k * N + n4 * 4);
        }
        CP_COMMIT();
    };

    load_chunk(0, 0);
    for (int c = 0; c < NC; c++) {
        const int st = c & 1;
        if (c + 1 < NC) { load_chunk(c + 1, (c + 1) & 1); CP_WAIT(1); }
        else            { CP_WAIT(0); }
        __syncthreads();

        const unsigned* smA = sm + st * STG_WORDS;
        const unsigned* smB = smA + A_WORDS;
#pragma unroll
        for (int ks = 0; ks < 32; ks += 8) {
            unsigned af[4][4], bf[4][2];
#pragma unroll
            for (int mt = 0; mt < 4; mt++) {
                int r0 = wm + mt * 16 + grp;
                af[mt][0] = smA[r0 * AST + ks + tig];
                af[mt][1] = smA[(r0 + 8) * AST + ks + tig];
                af[mt][2] = smA[r0 * AST + ks + tig + 4];
                af[mt][3] = smA[(r0 + 8) * AST + ks + tig + 4];
            }
#pragma unroll
            for (int nt = 0; nt < 4; nt++) {
                int c0 = wn + nt * 8 + grp;
                bf[nt][0] = smB[(ks + tig) * BST + c0];
                bf[nt][1] = smB[(ks + tig + 4) * BST + c0];
            }
#pragma unroll
            for (int mt = 0; mt < 4; mt++)
#pragma unroll
                for (int nt = 0; nt < 4; nt++)
                    mma_tf32(acc[mt][nt], af[mt], bf[nt]);
        }
        __syncthreads();
    }

    // epilogue
#pragma unroll
    for (int mt = 0; mt < 4; mt++) {
        int r0 = bm + wm + mt * 16 + grp;
#pragma unroll
        for (int nt = 0; nt < 4; nt++) {
            int c0 = bn + wn + nt * 8 + 2 * tig;
            float b0 = bias[c0], b1 = bias[c0 + 1];
            float v00 = acc[mt][nt][0] + b0, v01 = acc[mt][nt][1] + b1;
            float v10 = acc[mt][nt][2] + b0, v11 = acc[mt][nt][3] + b1;
            if (OUT_TF32) {
                unsigned* C = (unsigned*)Cout;
                *(uint2*)(C + (size_t)r0 * N + c0) = make_uint2(f2tf32(v00), f2tf32(v01));
                *(uint2*)(C + (size_t)(r0 + 8) * N + c0) = make_uint2(f2tf32(v10), f2tf32(v11));
            } else {
                float* C = (float*)Cout;
                *(float2*)(C + (size_t)r0 * N + c0) = make_float2(v00, v01);
                *(float2*)(C + (size_t)(r0 + 8) * N + c0) = make_float2(v10, v11);
            }
        }
    }
}

// ---------------- flash attention, tf32 mma, tf32-word I/O ----------------
#define QS_STRIDE 68
#define VS_STRIDE 72
#define SM_QOFF 0
#define SM_KOFF (64 * QS_STRIDE)
#define SM_VOFF (SM_KOFF + 64 * QS_STRIDE)
#define ATTN_SMEM_WORDS (SM_VOFF + 64 * VS_STRIDE)

__global__ __launch_bounds__(128) void gqa_attn_tf32_kernel(
    const unsigned* __restrict__ Q, const unsigned* __restrict__ Kb,
    const unsigned* __restrict__ Vb, unsigned* __restrict__ O)
{
    extern __shared__ unsigned sm[];
    unsigned* Qs  = sm + SM_QOFF;
    unsigned* KPs = sm + SM_KOFF;
    unsigned* Vs  = sm + SM_VOFF;

    const int h  = blockIdx.y;
    const int b  = blockIdx.z;
    const int g  = h >> 2;
    const int q0 = blockIdx.x * 64;
    const int tid  = threadIdx.x;
    const int warp = tid >> 5;
    const int lane = tid & 31;
    const int grp  = lane >> 2;
    const int tig  = lane & 3;
    const int rA = warp * 16 + grp;

    // load Q tile (already tf32 words)
    for (int e = tid; e < 1024; e += 128) {
        int q = e >> 4, d4 = e & 15;
        *(uint4*)&Qs[q * QS_STRIDE + d4 * 4] =
            *(const uint4*)(Q + (size_t)(b * SEQ + q0 + q) * DMODEL + h * DKH + d4 * 4);
    }

    float oacc[8][4];
#pragma unroll
    for (int nt = 0; nt < 8; nt++)
#pragma unroll
        for (int f = 0; f < 4; f++) oacc[nt][f] = 0.0f;
    float mA = -1e30f, mB = -1e30f, lA = 0.0f, lB = 0.0f;
    const float scale = 0.125f;

    for (int kt = 0; kt < SEQ; kt += 64) {
        for (int e = tid; e < 1024; e += 128) {
            int j = e >> 4, d4 = e & 15;
            size_t gidx = (size_t)(b * SEQ + kt + j) * GDK + g * DKH + d4 * 4;
            *(uint4*)&KPs[j * QS_STRIDE + d4 * 4] = *(const uint4*)(Kb + gidx);
            *(uint4*)&Vs[j * VS_STRIDE + d4 * 4]  = *(const uint4*)(Vb + gidx);
        }
        __syncthreads();

        float sacc[8][4];
#pragma unroll
        for (int nt = 0; nt < 8; nt++)
#pragma unroll
            for (int f = 0; f < 4; f++) sacc[nt][f] = 0.0f;

#pragma unroll
        for (int ks = 0; ks < 8; ks++) {
            int d = ks * 8;
            unsigned af[4];
            af[0] = Qs[rA * QS_STRIDE + d + tig];
            af[1] = Qs[(rA + 8) * QS_STRIDE + d + tig];
            af[2] = Qs[rA * QS_STRIDE + d + tig + 4];
            af[3] = Qs[(rA + 8) * QS_STRIDE + d + tig + 4];
#pragma unroll
            for (int nt = 0; nt < 8; nt++) {
                unsigned bf[2];
                bf[0] = KPs[(nt * 8 + grp) * QS_STRIDE + d + tig];
                bf[1] = KPs[(nt * 8 + grp) * QS_STRIDE + d + tig + 4];
                mma_tf32(sacc[nt], af, bf);
            }
        }
        __syncthreads();

        float rmaxA = -1e30f, rmaxB = -1e30f;
#pragma unroll
        for (int nt = 0; nt < 8; nt++) {
#pragma unroll
            for (int f = 0; f < 4; f++) sacc[nt][f] *= scale;
            rmaxA = fmaxf(rmaxA, fmaxf(sacc[nt][0], sacc[nt][1]));
            rmaxB = fmaxf(rmaxB, fmaxf(sacc[nt][2], sacc[nt][3]));
        }
#pragma unroll
        for (int o = 1; o <= 2; o <<= 1) {
            rmaxA = fmaxf(rmaxA, __shfl_xor_sync(0xffffffffu, rmaxA, o));
            rmaxB = fmaxf(rmaxB, __shfl_xor_sync(0xffffffffu, rmaxB, o));
        }
        float mnA = fmaxf(mA, rmaxA), mnB = fmaxf(mB, rmaxB);

        float lsA = 0.0f, lsB = 0.0f;
#pragma unroll
        for (int nt = 0; nt < 8; nt++) {
            float p0 = __expf(sacc[nt][0] - mnA);
            float p1 = __expf(sacc[nt][1] - mnA);
            float p2 = __expf(sacc[nt][2] - mnB);
            float p3 = __expf(sacc[nt][3] - mnB);
            lsA += p0 + p1;  lsB += p2 + p3;
            int c = nt * 8 + 2 * tig;
            KPs[rA * QS_STRIDE + c]           = f2tf32(p0);
            KPs[rA * QS_STRIDE + c + 1]       = f2tf32(p1);
            KPs[(rA + 8) * QS_STRIDE + c]     = f2tf32(p2);
            KPs[(rA + 8) * QS_STRIDE + c + 1] = f2tf32(p3);
        }
#pragma unroll
        for (int o = 1; o <= 2; o <<= 1) {
            lsA += __shfl_xor_sync(0xffffffffu, lsA, o);
            lsB += __shfl_xor_sync(0xffffffffu, lsB, o);
        }
        float alA = __expf(mA - mnA), alB = __expf(mB - mnB);
        lA = lA * alA + lsA;  lB = lB * alB + lsB;
        mA = mnA;             mB = mnB;
#pragma unroll
        for (int nt = 0; nt < 8; nt++) {
            oacc[nt][0] *= alA; oacc[nt][1] *= alA;
            oacc[nt][2] *= alB; oacc[nt][3] *= alB;
        }
        __syncwarp();

#pragma unroll
        for (int ks = 0; ks < 8; ks++) {
            int j = ks * 8;
            unsigned af[4];
            af[0] = KPs[rA * QS_STRIDE + j + tig];
            af[1] = KPs[(rA + 8) * QS_STRIDE + j + tig];
            af[2] = KPs[rA * QS_STRIDE + j + tig + 4];
            af[3] = KPs[(rA + 8) * QS_STRIDE + j + tig + 4];
#pragma unroll
            for (int nt = 0; nt < 8; nt++) {
                unsigned bf[2];
                bf[0] = Vs[(j + tig) * VS_STRIDE + nt * 8 + grp];
                bf[1] = Vs[(j + tig + 4) * VS_STRIDE + nt * 8 + grp];
                mma_tf32(oacc[nt], af, bf);
            }
        }
        __syncthreads();
    }

    // epilogue: write context as tf32 words
    float invA = 1.0f / lA, invB = 1.0f / lB;
    size_t rowA = (size_t)(b * SEQ + q0 + rA) * DMODEL + h * DKH;
    size_t rowB = rowA + (size_t)8 * DMODEL;
#pragma unroll
    for (int nt = 0; nt < 8; nt++) {
        int c = nt * 8 + 2 * tig;
        *(uint2*)(O + rowA + c) =
            make_uint2(f2tf32(oacc[nt][0] * invA), f2tf32(oacc[nt][1] * invA));
        *(uint2*)(O + rowB + c) =
            make_uint2(f2tf32(oacc[nt][2] * invB), f2tf32(oacc[nt][3] * invB));
    }
}

// ---------------- host ----------------
extern "C" void kernel_launch(void* const* d_in, const int* in_sizes, int n_in,
                              void* d_out, int out_size)
{
    const float* x  = (const float*)d_in[0];
    const float* Wq = (const float*)d_in[1];
    const float* bq = (const float*)d_in[2];
    const float* Wk = (const float*)d_in[3];
    const float* bk = (const float*)d_in[4];
    const float* Wv = (const float*)d_in[5];
    const float* bv = (const float*)d_in[6];
    const float* Wo = (const float*)d_in[7];
    const float* bo = (const float*)d_in[8];
    float* out = (float*)d_out;

    unsigned *xt, *Qt, *Kt, *Vt, *Ct, *Wqt, *Wkt, *Wvt, *Wot;
    cudaGetSymbolAddress((void**)&xt,  g_xt);
    cudaGetSymbolAddress((void**)&Qt,  g_Qt);
    cudaGetSymbolAddress((void**)&Kt,  g_Kt);
    cudaGetSymbolAddress((void**)&Vt,  g_Vt);
    cudaGetSymbolAddress((void**)&Ct,  g_Ct);
    cudaGetSymbolAddress((void**)&Wqt, g_Wqt);
    cudaGetSymbolAddress((void**)&Wkt, g_Wkt);
    cudaGetSymbolAddress((void**)&Wvt, g_Wvt);
    cudaGetSymbolAddress((void**)&Wot, g_Wot);

    const int attn_smem = ATTN_SMEM_WORDS * (int)sizeof(unsigned);
    cudaFuncSetAttribute(gqa_attn_tf32_kernel,
                         cudaFuncAttributeMaxDynamicSharedMemorySize, attn_smem);
    cudaFuncSetAttribute(gemm_tf32_cp_kernel<true>,
                         cudaFuncAttributeMaxDynamicSharedMemorySize, GEMM_SMEM);
    cudaFuncSetAttribute(gemm_tf32_cp_kernel<false>,
                         cudaFuncAttributeMaxDynamicSharedMemorySize, GEMM_SMEM);

    // one-time tf32 conversions
    cvt_tf32_kernel<<<(MROWS * DMODEL / 4 + 255) / 256, 256>>>(x,  xt,  MROWS * DMODEL / 4);
    cvt_tf32_kernel<<<(DMODEL * DMODEL / 4 + 255) / 256, 256>>>(Wq, Wqt, DMODEL * DMODEL / 4);
    cvt_tf32_kernel<<<(DMODEL * GDK / 4 + 255) / 256, 256>>>(Wk, Wkt, DMODEL * GDK / 4);
    cvt_tf32_kernel<<<(DMODEL * GDK / 4 + 255) / 256, 256>>>(Wv, Wvt, DMODEL * GDK / 4);
    cvt_tf32_kernel<<<(DMODEL * DMODEL / 4 + 255) / 256, 256>>>(Wo, Wot, DMODEL * DMODEL / 4);

    // projections -> tf32 Q/K/V
    gemm_tf32_cp_kernel<true><<<dim3(DMODEL / 128, MROWS / 128), 256, GEMM_SMEM>>>(
        xt, Wqt, bq, Qt, DMODEL, DMODEL);
    gemm_tf32_cp_kernel<true><<<dim3(GDK / 128, MROWS / 128), 256, GEMM_SMEM>>>(
        xt, Wkt, bk, Kt, GDK, DMODEL);
    gemm_tf32_cp_kernel<true><<<dim3(GDK / 128, MROWS / 128), 256, GEMM_SMEM>>>(
        xt, Wvt, bv, Vt, GDK, DMODEL);

    // attention -> tf32 context
    gqa_attn_tf32_kernel<<<dim3(SEQ / 64, NH, BATCH), 128, attn_smem>>>(Qt, Kt, Vt, Ct);

    // output projection -> fp32 out
    gemm_tf32_cp_kernel<false><<<dim3(DMODEL / 128, MROWS / 128), 256, GEMM_SMEM>>>(
        Ct, Wot, bo, out, DMODEL, DMODEL);
}